// round 15
// baseline (speedup 1.0000x reference)
#include <cuda_runtime.h>
#include <math.h>

#define BN 32768            // 16*2048 rows
typedef unsigned long long ull;

// U_g row layout: [u1(64) | u2(64)]  where u1=tanh(3*lin1(n1)), u2=tanh(3*lin2(n2))
__device__ float U_g[(size_t)BN * 128];

__device__ __forceinline__ ull pk2(float a, float b) {
    ull r; asm("mov.b64 %0, {%1, %2};" : "=l"(r) : "f"(a), "f"(b)); return r;
}
__device__ __forceinline__ void fma2(ull& d, ull a, ull b) {
    asm("fma.rn.f32x2 %0, %1, %2, %0;" : "+l"(d) : "l"(a), "l"(b));
}
__device__ __forceinline__ void unpk2(ull v, float& lo, float& hi) {
    asm("mov.b64 {%0, %1}, %2;" : "=f"(lo), "=f"(hi) : "l"(v));
}

// ---------------------------------------------------------------------------
// Bit-exact replica of XLA llvm_ir::EmitFastTanh WITH_FMA variant (FMA-capable
// target, e.g. Grace/aarch64):
//   |x| < 0.0004 -> x ; clamp to +-7.99881172180175781 ; odd/even rational
//   with FUSED fma Horner ; plain mul for x*p ; IEEE divide.
// ---------------------------------------------------------------------------
__device__ __forceinline__ float xla_tanh(float x) {
    float ax = fabsf(x);
    float xc = fminf(fmaxf(x, -7.99881172180175781f), 7.99881172180175781f);
    float x2 = __fmul_rn(xc, xc);
    float p = -2.76076847742355e-16f;
    p = fmaf(x2, p, 2.00018790482477e-13f);
    p = fmaf(x2, p, -8.60467152213735e-11f);
    p = fmaf(x2, p, 5.12229709037114e-08f);
    p = fmaf(x2, p, 1.48572235717979e-05f);
    p = fmaf(x2, p, 6.37261928875436e-04f);
    p = fmaf(x2, p, 4.89352455891786e-03f);
    float num = __fmul_rn(xc, p);
    float q = 1.19825839466702e-06f;
    q = fmaf(x2, q, 1.18534705686654e-04f);
    q = fmaf(x2, q, 2.26843463243900e-03f);
    q = fmaf(x2, q, 4.89352518554385e-03f);
    float r = __fdiv_rn(num, q);
    return (ax < 0.0004f) ? x : r;
}

// ---------------------------------------------------------------------------
// Bit-exact replica of XLA-CPU GenerateVF32Exp on an FMA target: the emitter
// uses VectorSupportLibrary::MulAdd == llvm.fmuladd, which aarch64 contracts
// to FUSED fma. Cephes algorithm:
//   m = floor(fma(x, log2e, 0.5));
//   x = fma(-m, 0.693359375, x); x = fma(m, 2.12194440e-4, x);   (Cody-Waite)
//   deg-5 fused-Horner; y = fma(p, x^2, x) + 1; scale by 2^m (bit trick).
// Inputs here are |x| < ~15, far from the clamp range, so clamps omitted.
// ---------------------------------------------------------------------------
__device__ __forceinline__ float cephes_expf(float x) {
    float m = floorf(fmaf(x, 1.44269504088896341f, 0.5f));
    x = fmaf(-m, 0.693359375f, x);
    x = fmaf(m, 2.12194440e-4f, x);
    float x2 = __fmul_rn(x, x);
    float y = 1.9875691500e-4f;
    y = fmaf(y, x, 1.3981999507e-3f);
    y = fmaf(y, x, 8.3334519073e-3f);
    y = fmaf(y, x, 4.1665795894e-2f);
    y = fmaf(y, x, 1.6666665459e-1f);
    y = fmaf(y, x, 5.0000001201e-1f);
    y = fmaf(y, x2, x);
    y = __fadd_rn(y, 1.0f);
    int n = (int)m;
    float s = __uint_as_float((unsigned)(n + 127) << 23);
    return __fmul_rn(y, s);
}

// XLA LogisticExpander exp form: logistic(x) = 1 / (1 + exp(-x))
__device__ __forceinline__ float xla_sigmoid(float x) {
    return __fdiv_rn(1.0f, __fadd_rn(1.0f, cephes_expf(-x)));
}

// ---------------------------------------------------------------------------
// Stage 1: per-row gating + MLPs -> U_g=[u1|u2]
// Dots: ascending-d sequential FFMA from 0 (Eigen gebp order); bias added
// after; elementwise ops individually rounded (no contraction).
// ---------------------------------------------------------------------------
#define S1_SMEM (18688 * 4)

__global__ __launch_bounds__(256, 2) void k_stage1(
    const int* __restrict__ idx, const float* __restrict__ emb,
    const float* __restrict__ W1, const float* __restrict__ b1,
    const float* __restrict__ W2, const float* __restrict__ b2,
    const float* __restrict__ Wgs, const float* __restrict__ bgs,
    const float* __restrict__ Wgd, const float* __restrict__ bgd,
    const float* __restrict__ emb1, const float* __restrict__ emb2)
{
    extern __shared__ float sm1[];
    float* smw = sm1;                 // 4 matrices [64][68]
    float* xg  = sm1 + 17408;
    float* s1g = xg + 256;
    float* s2g = s1g + 256;
    float* n1s = s2g + 256;
    float* n2s = n1s + 256;
    const int t = threadIdx.x;

    for (int i = t; i < 4 * 4096; i += 256) {
        int mat = i >> 12, e = i & 4095, jj = e >> 6, dd = e & 63;
        const float* src = (mat == 0) ? Wgd : (mat == 1) ? Wgs : (mat == 2) ? W1 : W2;
        smw[mat * 4352 + jj * 68 + dd] = src[e];
    }
    __syncthreads();

    const int rr = t >> 6, j = t & 63;
    const float bgdj = bgd[j], bgsj = bgs[j], b1j = b1[j], b2j = b2[j];
    const int base = blockIdx.x * 128;

    for (int it = 0; it < 32; ++it) {
        const int gr0 = base + it * 4;
        {
            int grow = gr0 + rr;
            int n = grow & 2047;
            int node = idx[n];
            xg [rr * 64 + j] = emb [(size_t)grow * 64 + j];
            s1g[rr * 64 + j] = emb1[(size_t)node * 64 + j];
            s2g[rr * 64 + j] = emb2[(size_t)node * 64 + j];
        }
        __syncthreads();

        float gd = 0.0f, a1 = 0.0f, a2 = 0.0f;
        #pragma unroll
        for (int d4 = 0; d4 < 64; d4 += 4) {
            float4 wd = *(const float4*)(smw +        j * 68 + d4);
            float4 ws = *(const float4*)(smw + 4352 + j * 68 + d4);
            float4 xv = *(const float4*)(xg  + rr * 64 + d4);
            float4 v1 = *(const float4*)(s1g + rr * 64 + d4);
            float4 v2 = *(const float4*)(s2g + rr * 64 + d4);
            gd = fmaf(xv.x, wd.x, gd); gd = fmaf(xv.y, wd.y, gd);
            gd = fmaf(xv.z, wd.z, gd); gd = fmaf(xv.w, wd.w, gd);
            a1 = fmaf(v1.x, ws.x, a1); a1 = fmaf(v1.y, ws.y, a1);
            a1 = fmaf(v1.z, ws.z, a1); a1 = fmaf(v1.w, ws.w, a1);
            a2 = fmaf(v2.x, ws.x, a2); a2 = fmaf(v2.y, ws.y, a2);
            a2 = fmaf(v2.z, ws.z, a2); a2 = fmaf(v2.w, ws.w, a2);
        }
        float lind = __fadd_rn(gd, bgdj);                    // gate_dyn
        float z1 = __fadd_rn(__fadd_rn(a1, bgsj), lind);
        float z2 = __fadd_rn(__fadd_rn(a2, bgsj), lind);
        float g1 = xla_sigmoid(z1);
        float g2 = xla_sigmoid(z2);
        float xvj  = xg [rr * 64 + j];
        float sv1j = s1g[rr * 64 + j];
        float sv2j = s2g[rr * 64 + j];
        n1s[rr * 64 + j] = __fadd_rn(__fmul_rn(__fsub_rn(1.0f, g1), xvj),
                                     __fmul_rn(g1, sv1j));
        n2s[rr * 64 + j] = __fadd_rn(__fmul_rn(__fsub_rn(1.0f, g2), xvj),
                                     __fmul_rn(g2, sv2j));
        __syncthreads();

        float c1 = 0.0f, c2 = 0.0f;
        #pragma unroll
        for (int d4 = 0; d4 < 64; d4 += 4) {
            float4 w1v = *(const float4*)(smw + 2*4352 + j * 68 + d4);
            float4 w2v = *(const float4*)(smw + 3*4352 + j * 68 + d4);
            float4 p1  = *(const float4*)(n1s + rr * 64 + d4);
            float4 p2  = *(const float4*)(n2s + rr * 64 + d4);
            c1 = fmaf(p1.x, w1v.x, c1); c1 = fmaf(p1.y, w1v.y, c1);
            c1 = fmaf(p1.z, w1v.z, c1); c1 = fmaf(p1.w, w1v.w, c1);
            c2 = fmaf(p2.x, w2v.x, c2); c2 = fmaf(p2.y, w2v.y, c2);
            c2 = fmaf(p2.z, w2v.z, c2); c2 = fmaf(p2.w, w2v.w, c2);
        }
        float u1 = xla_tanh(__fmul_rn(3.0f, __fadd_rn(c1, b1j)));
        float u2 = xla_tanh(__fmul_rn(3.0f, __fadd_rn(c2, b2j)));
        size_t ub = (size_t)(gr0 + rr) * 128;
        U_g[ub + j] = u1;  U_g[ub + 64 + j] = u2;
        __syncthreads();
    }
}

// ---------------------------------------------------------------------------
// Stage 2: a[n,m] = seqdot(u1[n],u2[m]) - seqdot(u2[n],u1[m]) fused with
// xla_tanh/relu + tie-exact top-20 + masked output.
// 512 blocks (64-row slab) x 128 threads, 2 blocks/SM. Tile 8n x 8m.
// ---------------------------------------------------------------------------
#define S2_SMEM (28416 * 4)

// Streaming top-20 equivalent to jax.lax.top_k ordering (key desc, index asc):
// evict the min-key entry, choosing the HIGHEST index among tied minima;
// caller rejects new candidates with key <= thr (new index is always larger).
__device__ __forceinline__ float insert20(float* Lk, int* Li, float* Lv,
                                          float key, int index, float val) {
    float mn = Lk[0]; int mp = 0;
    #pragma unroll
    for (int i = 1; i < 20; ++i) {
        float ki = Lk[i];
        if (ki < mn || (ki == mn && Li[i] > Li[mp])) { mn = ki; mp = i; }
    }
    Lk[mp] = key; Li[mp] = index; Lv[mp] = val;
    float nm = Lk[0];
    #pragma unroll
    for (int i = 1; i < 20; ++i) nm = fminf(nm, Lk[i]);
    return nm;
}

__global__ __launch_bounds__(128, 2) void k_stage2(
    const float* __restrict__ noise, float* __restrict__ out)
{
    extern __shared__ float sm[];
    float* Us1  = sm;                 // [k=64][n=64]
    float* Us2  = sm + 4096;
    float* Vs1  = sm + 8192;          // [k=64][m=128]
    float* Vs2  = sm + 16384;
    float* Sp   = sm + 8192;          // score overlay [64][132] over Vs
    float* Lkey = sm + 24576;         // [64][20]
    int*   Lidx = (int*)(sm + 25856);
    float* Lval = sm + 27136;

    const int t = threadIdx.x;
    const int slab = blockIdx.x;
    const int b = slab >> 5;
    const int n0 = (slab & 31) << 6;
    const int tx = t & 15;
    const int ty = t >> 4;

    const float* Ub = U_g + (size_t)slab * (64 * 128);
    for (int i = t; i < 2048; i += 128) {
        int nl = i & 63, c = (i >> 6) << 2;
        float4 u4 = *(const float4*)(Ub + (size_t)nl * 128 + c);
        float* dst = (c < 64) ? (Us1 + c * 64) : (Us2 + (c - 64) * 64);
        dst[0 * 64 + nl] = u4.x;
        dst[1 * 64 + nl] = u4.y;
        dst[2 * 64 + nl] = u4.z;
        dst[3 * 64 + nl] = u4.w;
    }
    for (int i = t; i < 64 * 20; i += 128) { Lkey[i] = -1e30f; Lidx[i] = 0; }

    const float* up1 = Us1 + ty * 8;
    const float* up2 = Us2 + ty * 8;
    const float* vp1 = Vs1 + 2 * tx;
    const float* vp2 = Vs2 + 2 * tx;
    float thr = -1e30f;

    for (int mt = 0; mt < 16; ++mt) {
        __syncthreads();
        const float* Vb = U_g + ((size_t)b * 2048 + mt * 128) * 128;
        for (int i = t; i < 4096; i += 128) {
            int ml = i & 127, c = (i >> 7) << 2;
            float4 v4 = *(const float4*)(Vb + (size_t)ml * 128 + c);
            float* dst = (c < 64) ? (Vs1 + c * 128) : (Vs2 + (c - 64) * 128);
            dst[0 * 128 + ml] = v4.x;
            dst[1 * 128 + ml] = v4.y;
            dst[2 * 128 + ml] = v4.z;
            dst[3 * 128 + ml] = v4.w;
        }
        __syncthreads();

        ull acc1[8][4], acc2[8][4];
        #pragma unroll
        for (int i = 0; i < 8; ++i)
            #pragma unroll
            for (int j = 0; j < 4; ++j) { acc1[i][j] = 0ull; acc2[i][j] = 0ull; }

        #pragma unroll 4
        for (int k = 0; k < 64; ++k) {
            float4 ua = *(const float4*)(up1 + k * 64);
            float4 ub4 = *(const float4*)(up1 + k * 64 + 4);
            float4 wa = *(const float4*)(up2 + k * 64);
            float4 wb = *(const float4*)(up2 + k * 64 + 4);
            ull du1[8], du2[8];
            du1[0] = pk2(ua.x, ua.x);   du1[1] = pk2(ua.y, ua.y);
            du1[2] = pk2(ua.z, ua.z);   du1[3] = pk2(ua.w, ua.w);
            du1[4] = pk2(ub4.x, ub4.x); du1[5] = pk2(ub4.y, ub4.y);
            du1[6] = pk2(ub4.z, ub4.z); du1[7] = pk2(ub4.w, ub4.w);
            du2[0] = pk2(wa.x, wa.x);   du2[1] = pk2(wa.y, wa.y);
            du2[2] = pk2(wa.z, wa.z);   du2[3] = pk2(wa.w, wa.w);
            du2[4] = pk2(wb.x, wb.x);   du2[5] = pk2(wb.y, wb.y);
            du2[6] = pk2(wb.z, wb.z);   du2[7] = pk2(wb.w, wb.w);
            const float* vk1 = vp1 + k * 128;
            const float* vk2 = vp2 + k * 128;
            ull vv1[4], vv2[4];
            vv1[0] = *(const ull*)(vk1);      vv2[0] = *(const ull*)(vk2);
            vv1[1] = *(const ull*)(vk1 + 32); vv2[1] = *(const ull*)(vk2 + 32);
            vv1[2] = *(const ull*)(vk1 + 64); vv2[2] = *(const ull*)(vk2 + 64);
            vv1[3] = *(const ull*)(vk1 + 96); vv2[3] = *(const ull*)(vk2 + 96);
            #pragma unroll
            for (int i = 0; i < 8; ++i)
                #pragma unroll
                for (int j = 0; j < 4; ++j) {
                    fma2(acc1[i][j], du1[i], vv2[j]);   // u1[n]*u2[m]
                    fma2(acc2[i][j], du2[i], vv1[j]);   // u2[n]*u1[m]
                }
        }
        __syncthreads();

        #pragma unroll
        for (int i = 0; i < 8; ++i) {
            int n = ty * 8 + i;
            #pragma unroll
            for (int j = 0; j < 4; ++j) {
                int m0 = 2 * (tx + 16 * j);
                float lo1, hi1, lo2, hi2;
                unpk2(acc1[i][j], lo1, hi1);
                unpk2(acc2[i][j], lo2, hi2);
                float alo = __fsub_rn(lo1, lo2);
                float ahi = __fsub_rn(hi1, hi2);
                float2 sc;
                sc.x = fmaxf(xla_tanh(__fmul_rn(3.0f, alo)), 0.0f);
                sc.y = fmaxf(xla_tanh(__fmul_rn(3.0f, ahi)), 0.0f);
                *(float2*)(Sp + n * 132 + m0) = sc;
            }
        }
        {
            float4 z = make_float4(0.f, 0.f, 0.f, 0.f);
            float* ob = out + ((size_t)(b * 2048 + n0)) * 2048 + mt * 128;
            for (int i = t; i < 2048; i += 128) {
                int row = i >> 5, c4 = (i & 31) << 2;
                *(float4*)(ob + (size_t)row * 2048 + c4) = z;
            }
        }
        __syncthreads();

        if (t < 64) {
            const int r = t;
            const float* nz = noise + ((size_t)(b * 2048 + n0 + r)) * 2048 + mt * 128;
            const float* Sr = Sp + r * 132;
            float* Lk = Lkey + r * 20;
            int*   Li = Lidx + r * 20;
            float* Lv = Lval + r * 20;
            for (int m4 = 0; m4 < 128; m4 += 4) {
                float4 nv = *(const float4*)(nz + m4);
                float4 sv = *(const float4*)(Sr + m4);
                int mg = mt * 128 + m4;
                float k0 = __fadd_rn(sv.x, __fmul_rn(nv.x, 0.01f));
                float k1 = __fadd_rn(sv.y, __fmul_rn(nv.y, 0.01f));
                float k2 = __fadd_rn(sv.z, __fmul_rn(nv.z, 0.01f));
                float k3 = __fadd_rn(sv.w, __fmul_rn(nv.w, 0.01f));
                if (k0 > thr) thr = insert20(Lk, Li, Lv, k0, mg,     sv.x);
                if (k1 > thr) thr = insert20(Lk, Li, Lv, k1, mg + 1, sv.y);
                if (k2 > thr) thr = insert20(Lk, Li, Lv, k2, mg + 2, sv.z);
                if (k3 > thr) thr = insert20(Lk, Li, Lv, k3, mg + 3, sv.w);
            }
        }
    }
    __syncthreads();
    if (t < 64) {
        float* orow = out + ((size_t)(b * 2048 + n0 + t)) * 2048;
        #pragma unroll
        for (int i = 0; i < 20; ++i)
            orow[Lidx[t * 20 + i]] = Lval[t * 20 + i];
    }
}

// ---------------------------------------------------------------------------
extern "C" void kernel_launch(void* const* d_in, const int* in_sizes, int n_in,
                              void* d_out, int out_size) {
    (void)in_sizes; (void)n_in; (void)out_size;
    const int*   idx  = (const int*)  d_in[0];
    const float* emb  = (const float*)d_in[1];
    const float* nois = (const float*)d_in[2];
    const float* W1   = (const float*)d_in[3];
    const float* b1   = (const float*)d_in[4];
    const float* W2   = (const float*)d_in[5];
    const float* b2   = (const float*)d_in[6];
    const float* Wgs  = (const float*)d_in[7];
    const float* bgs  = (const float*)d_in[8];
    const float* Wgd  = (const float*)d_in[9];
    const float* bgd  = (const float*)d_in[10];
    const float* emb1 = (const float*)d_in[11];
    const float* emb2 = (const float*)d_in[12];
    float* out = (float*)d_out;

    cudaFuncSetAttribute(k_stage1, cudaFuncAttributeMaxDynamicSharedMemorySize, S1_SMEM);
    cudaFuncSetAttribute(k_stage2, cudaFuncAttributeMaxDynamicSharedMemorySize, S2_SMEM);

    k_stage1<<<256, 256, S1_SMEM>>>(idx, emb, W1, b1, W2, b2,
                                    Wgs, bgs, Wgd, bgd, emb1, emb2);
    k_stage2<<<512, 128, S2_SMEM>>>(nois, out);
}